// round 1
// baseline (speedup 1.0000x reference)
#include <cuda_runtime.h>
#include <cstdint>

#define BB 65536
#define HH 512
#define SS 256
#define DD 64
#define TB 64

// shared-memory layout (float offsets)
#define QS_OFF   0        // [32][65]   Q chunk, k-major, padded
#define WS_OFF   2080     // [32][257]  W chunk, k-major, padded
#define PT_OFF   10304    // [64][260]  softmax probs (read pass), padded
#define MS_OFF   26944    // [256][65]  memory tile (tf32), padded
#define BIAS_OFF 43584    // [256]
#define RED_OFF  43840    // [64][4]
#define RMAX_OFF 44096    // [64]
#define RSUM_OFF 44160    // [64]
#define SMEM_F   44224
#define SMEM_BYTES (SMEM_F * 4)

__device__ float g_wsum[SS];
__device__ float g_csum[HH];

__device__ __forceinline__ float tff(float x) {
    uint32_t u;
    asm("cvt.rna.tf32.f32 %0, %1;" : "=r"(u) : "f"(x));
    return __uint_as_float(u);
}

__device__ __forceinline__ void mma8(float c[4], const uint32_t a[4], uint32_t b0, uint32_t b1) {
    asm volatile(
        "mma.sync.aligned.m16n8k8.row.col.f32.tf32.tf32.f32 "
        "{%0,%1,%2,%3},{%4,%5,%6,%7},{%8,%9},{%0,%1,%2,%3};\n"
        : "+f"(c[0]), "+f"(c[1]), "+f"(c[2]), "+f"(c[3])
        : "r"(a[0]), "r"(a[1]), "r"(a[2]), "r"(a[3]), "r"(b0), "r"(b1));
}

__global__ void k_init() {
    int i = threadIdx.x;          // 256 threads
    g_wsum[i] = 0.f;
    g_csum[i] = 0.f;
    g_csum[i + 256] = 0.f;
}

// column sums of content [B, H] -> g_csum[H]
__global__ __launch_bounds__(256) void k_colsum(const float* __restrict__ C) {
    int tid = threadIdx.x;
    int col = (tid & 127) << 2;   // float4 column
    int rg  = tid >> 7;           // 0 or 1
    size_t r0 = (size_t)blockIdx.x * 128;
    float ax = 0.f, ay = 0.f, az = 0.f, aw = 0.f;
    for (int r = rg; r < 128; r += 2) {
        float4 v = *reinterpret_cast<const float4*>(C + (r0 + r) * HH + col);
        ax += v.x; ay += v.y; az += v.z; aw += v.w;
    }
    atomicAdd(&g_csum[col + 0], ax);
    atomicAdd(&g_csum[col + 1], ay);
    atomicAdd(&g_csum[col + 2], az);
    atomicAdd(&g_csum[col + 3], aw);
}

// Fused: logits GEMM (tf32 mma) + bias + softmax + (pass0: probs@memory -> read_content,
// pass1: column-sum of probs -> g_wsum)
__global__ __launch_bounds__(256, 1) void k_main(
    const float* __restrict__ Q,  const float* __restrict__ Wr, const float* __restrict__ br,
    const float* __restrict__ Ww, const float* __restrict__ bw, const float* __restrict__ Mem,
    float* __restrict__ out_rc)
{
    extern __shared__ float smf[];
    float* Qs    = smf + QS_OFF;
    float* Ws    = smf + WS_OFF;
    float* Pt    = smf + PT_OFF;
    float* Ms    = smf + MS_OFF;
    float* sbias = smf + BIAS_OFF;
    float* sred  = smf + RED_OFF;
    float* srmax = smf + RMAX_OFF;
    float* srsum = smf + RSUM_OFF;

    const int tid  = threadIdx.x;
    const int lane = tid & 31;
    const int g    = lane >> 2;
    const int t    = lane & 3;
    const int warp = tid >> 5;
    const int wm   = warp >> 2;   // 0..1
    const int wn   = warp & 3;    // 0..3
    const int m0   = blockIdx.x * TB;

    // memory tile -> smem (tf32-rounded), layout [k=slot][d], stride 65
    for (int j = tid; j < (SS * DD) / 4; j += 256) {
        int s = j >> 4, d = (j & 15) << 2;
        float4 v = *reinterpret_cast<const float4*>(Mem + s * DD + d);
        float* p = Ms + s * 65 + d;
        p[0] = tff(v.x); p[1] = tff(v.y); p[2] = tff(v.z); p[3] = tff(v.w);
    }

    for (int pass = 0; pass < 2; ++pass) {
        const float* Wp = pass ? Ww : Wr;
        const float* bp = pass ? bw : br;
        __syncthreads();
        sbias[tid] = bp[tid];

        float acc[2][8][4];
        #pragma unroll
        for (int mf = 0; mf < 2; ++mf)
            #pragma unroll
            for (int nf = 0; nf < 8; ++nf)
                #pragma unroll
                for (int e = 0; e < 4; ++e) acc[mf][nf][e] = 0.f;

        for (int kc = 0; kc < HH; kc += 32) {
            __syncthreads();
            // Q chunk: 64 rows x 32 k, stored transposed Qs[k][m]
            #pragma unroll
            for (int it = 0; it < 2; ++it) {
                int j = tid + it * 256;
                int r = j >> 3, c4 = (j & 7) << 2;
                float4 v = *reinterpret_cast<const float4*>(Q + (size_t)(m0 + r) * HH + kc + c4);
                Qs[(c4 + 0) * 65 + r] = tff(v.x);
                Qs[(c4 + 1) * 65 + r] = tff(v.y);
                Qs[(c4 + 2) * 65 + r] = tff(v.z);
                Qs[(c4 + 3) * 65 + r] = tff(v.w);
            }
            // W chunk: 32 k-rows x 256 slots, Ws[k][n]
            #pragma unroll
            for (int it = 0; it < 8; ++it) {
                int j = tid + it * 256;
                int r = j >> 6, c4 = (j & 63) << 2;
                float4 v = *reinterpret_cast<const float4*>(Wp + (size_t)(kc + r) * SS + c4);
                float* p = Ws + r * 257 + c4;
                p[0] = tff(v.x); p[1] = tff(v.y); p[2] = tff(v.z); p[3] = tff(v.w);
            }
            __syncthreads();
            #pragma unroll
            for (int kk = 0; kk < 32; kk += 8) {
                uint32_t a[2][4];
                #pragma unroll
                for (int mf = 0; mf < 2; ++mf) {
                    int rb = wm * 32 + mf * 16;
                    a[mf][0] = __float_as_uint(Qs[(kk + t) * 65     + rb + g]);
                    a[mf][1] = __float_as_uint(Qs[(kk + t) * 65     + rb + g + 8]);
                    a[mf][2] = __float_as_uint(Qs[(kk + t + 4) * 65 + rb + g]);
                    a[mf][3] = __float_as_uint(Qs[(kk + t + 4) * 65 + rb + g + 8]);
                }
                #pragma unroll
                for (int nf = 0; nf < 8; ++nf) {
                    int cb = wn * 64 + nf * 8;
                    uint32_t b0 = __float_as_uint(Ws[(kk + t) * 257     + cb + g]);
                    uint32_t b1 = __float_as_uint(Ws[(kk + t + 4) * 257 + cb + g]);
                    mma8(acc[0][nf], a[0], b0, b1);
                    mma8(acc[1][nf], a[1], b0, b1);
                }
            }
        }

        // bias
        #pragma unroll
        for (int mf = 0; mf < 2; ++mf)
            #pragma unroll
            for (int nf = 0; nf < 8; ++nf) {
                int cb = wn * 64 + nf * 8 + 2 * t;
                acc[mf][nf][0] += sbias[cb];
                acc[mf][nf][1] += sbias[cb + 1];
                acc[mf][nf][2] += sbias[cb];
                acc[mf][nf][3] += sbias[cb + 1];
            }

        // local row ids: lr = mf*2 + hi
        int rowl[4];
        #pragma unroll
        for (int lr = 0; lr < 4; ++lr) rowl[lr] = wm * 32 + (lr >> 1) * 16 + (lr & 1) * 8 + g;

        // ---- row max ----
        float rmx[4] = {-3.0e38f, -3.0e38f, -3.0e38f, -3.0e38f};
        #pragma unroll
        for (int mf = 0; mf < 2; ++mf)
            #pragma unroll
            for (int nf = 0; nf < 8; ++nf) {
                rmx[mf * 2 + 0] = fmaxf(rmx[mf * 2 + 0], fmaxf(acc[mf][nf][0], acc[mf][nf][1]));
                rmx[mf * 2 + 1] = fmaxf(rmx[mf * 2 + 1], fmaxf(acc[mf][nf][2], acc[mf][nf][3]));
            }
        #pragma unroll
        for (int lr = 0; lr < 4; ++lr) {
            rmx[lr] = fmaxf(rmx[lr], __shfl_xor_sync(0xffffffffu, rmx[lr], 1));
            rmx[lr] = fmaxf(rmx[lr], __shfl_xor_sync(0xffffffffu, rmx[lr], 2));
        }
        if (t == 0) {
            #pragma unroll
            for (int lr = 0; lr < 4; ++lr) sred[rowl[lr] * 4 + wn] = rmx[lr];
        }
        __syncthreads();
        if (tid < 64) {
            float m01 = fmaxf(sred[tid * 4 + 0], sred[tid * 4 + 1]);
            float m23 = fmaxf(sred[tid * 4 + 2], sred[tid * 4 + 3]);
            srmax[tid] = fmaxf(m01, m23);
        }
        __syncthreads();

        // ---- exp + row sum ----
        float rm[4], rs[4] = {0.f, 0.f, 0.f, 0.f};
        #pragma unroll
        for (int lr = 0; lr < 4; ++lr) rm[lr] = srmax[rowl[lr]];
        #pragma unroll
        for (int mf = 0; mf < 2; ++mf)
            #pragma unroll
            for (int nf = 0; nf < 8; ++nf)
                #pragma unroll
                for (int e = 0; e < 4; ++e) {
                    int lr = mf * 2 + (e >> 1);
                    float v = __expf(acc[mf][nf][e] - rm[lr]);
                    acc[mf][nf][e] = v;
                    rs[lr] += v;
                }
        #pragma unroll
        for (int lr = 0; lr < 4; ++lr) {
            rs[lr] += __shfl_xor_sync(0xffffffffu, rs[lr], 1);
            rs[lr] += __shfl_xor_sync(0xffffffffu, rs[lr], 2);
        }
        if (t == 0) {
            #pragma unroll
            for (int lr = 0; lr < 4; ++lr) sred[rowl[lr] * 4 + wn] = rs[lr];
        }
        __syncthreads();
        if (tid < 64)
            srsum[tid] = sred[tid * 4 + 0] + sred[tid * 4 + 1] + sred[tid * 4 + 2] + sred[tid * 4 + 3];
        __syncthreads();
        float rinv[4];
        #pragma unroll
        for (int lr = 0; lr < 4; ++lr) rinv[lr] = 1.0f / srsum[rowl[lr]];

        if (pass == 0) {
            // probs -> smem (tf32)
            #pragma unroll
            for (int mf = 0; mf < 2; ++mf)
                #pragma unroll
                for (int nf = 0; nf < 8; ++nf) {
                    int cb = wn * 64 + nf * 8 + 2 * t;
                    Pt[rowl[mf * 2 + 0] * 260 + cb]     = tff(acc[mf][nf][0] * rinv[mf * 2 + 0]);
                    Pt[rowl[mf * 2 + 0] * 260 + cb + 1] = tff(acc[mf][nf][1] * rinv[mf * 2 + 0]);
                    Pt[rowl[mf * 2 + 1] * 260 + cb]     = tff(acc[mf][nf][2] * rinv[mf * 2 + 1]);
                    Pt[rowl[mf * 2 + 1] * 260 + cb + 1] = tff(acc[mf][nf][3] * rinv[mf * 2 + 1]);
                }
            __syncthreads();

            // read_content = probs[64,256] @ memory[256,64]
            float c2[2][2][4];
            #pragma unroll
            for (int mf = 0; mf < 2; ++mf)
                #pragma unroll
                for (int nf = 0; nf < 2; ++nf)
                    #pragma unroll
                    for (int e = 0; e < 4; ++e) c2[mf][nf][e] = 0.f;
            #pragma unroll 4
            for (int k = 0; k < SS; k += 8) {
                uint32_t a[2][4];
                #pragma unroll
                for (int mf = 0; mf < 2; ++mf) {
                    int rb = wm * 32 + mf * 16;
                    a[mf][0] = __float_as_uint(Pt[(rb + g) * 260     + k + t]);
                    a[mf][1] = __float_as_uint(Pt[(rb + g + 8) * 260 + k + t]);
                    a[mf][2] = __float_as_uint(Pt[(rb + g) * 260     + k + t + 4]);
                    a[mf][3] = __float_as_uint(Pt[(rb + g + 8) * 260 + k + t + 4]);
                }
                #pragma unroll
                for (int nf = 0; nf < 2; ++nf) {
                    int cb = wn * 16 + nf * 8;
                    uint32_t b0 = __float_as_uint(Ms[(k + t) * 65     + cb + g]);
                    uint32_t b1 = __float_as_uint(Ms[(k + t + 4) * 65 + cb + g]);
                    mma8(c2[0][nf], a[0], b0, b1);
                    mma8(c2[1][nf], a[1], b0, b1);
                }
            }
            #pragma unroll
            for (int mf = 0; mf < 2; ++mf)
                #pragma unroll
                for (int nf = 0; nf < 2; ++nf) {
                    size_t rb = (size_t)(m0 + wm * 32 + mf * 16);
                    int cb = wn * 16 + nf * 8 + 2 * t;
                    out_rc[(rb + g) * DD + cb]         = c2[mf][nf][0];
                    out_rc[(rb + g) * DD + cb + 1]     = c2[mf][nf][1];
                    out_rc[(rb + g + 8) * DD + cb]     = c2[mf][nf][2];
                    out_rc[(rb + g + 8) * DD + cb + 1] = c2[mf][nf][3];
                }
        } else {
            // write pass: only the column sums of probs are needed
            #pragma unroll
            for (int nf = 0; nf < 8; ++nf)
                #pragma unroll
                for (int jj = 0; jj < 2; ++jj) {
                    float v = acc[0][nf][jj]     * rinv[0] + acc[0][nf][jj + 2] * rinv[1]
                            + acc[1][nf][jj]     * rinv[2] + acc[1][nf][jj + 2] * rinv[3];
                    v += __shfl_xor_sync(0xffffffffu, v, 4);
                    v += __shfl_xor_sync(0xffffffffu, v, 8);
                    v += __shfl_xor_sync(0xffffffffu, v, 16);
                    if (lane < 4) atomicAdd(&g_wsum[wn * 64 + nf * 8 + 2 * t + jj], v);
                }
        }
    }
}

__global__ __launch_bounds__(256) void k_epilogue(
    const float* __restrict__ Mem, const float* __restrict__ age,
    const float* __restrict__ Wc,  const float* __restrict__ bc,
    float* __restrict__ out)
{
    __shared__ float cmean[DD];
    const int tid = threadIdx.x;
    const float invB = 1.0f / (float)BB;

    if (tid < DD) {
        float s = 0.f;
        #pragma unroll 8
        for (int h = 0; h < HH; ++h) s += g_csum[h] * Wc[h * DD + tid];
        cmean[tid] = s * invB + bc[tid];
    }
    __syncthreads();

    float* out_mem = out + (size_t)BB * DD;
    float* out_age = out_mem + SS * DD;

    for (int i = tid; i < SS * DD; i += 256) {
        int s = i >> 6, d = i & 63;
        float wmn = g_wsum[s] * invB;
        float a = 0.f;
        if (wmn > 0.01f) {
            float cons = 1.0f / (1.0f + __expf(-age[s] * 0.1f));
            a = wmn * cons;
        }
        out_mem[i] = (1.0f - a) * Mem[i] + a * cmean[d];
    }
    for (int s = tid; s < SS; s += 256) {
        float wmn = g_wsum[s] * invB;
        out_age[s] = age[s] + (wmn > 0.01f ? 1.0f : 0.0f);
    }
}

extern "C" void kernel_launch(void* const* d_in, const int* in_sizes, int n_in,
                              void* d_out, int out_size) {
    (void)in_sizes; (void)n_in; (void)out_size;
    const float* Q   = (const float*)d_in[0];
    const float* Ct  = (const float*)d_in[1];
    const float* Mem = (const float*)d_in[2];
    const float* age = (const float*)d_in[3];
    const float* Wr  = (const float*)d_in[4];
    const float* br  = (const float*)d_in[5];
    const float* Ww  = (const float*)d_in[6];
    const float* bw  = (const float*)d_in[7];
    const float* Wc  = (const float*)d_in[8];
    const float* bc  = (const float*)d_in[9];
    float* out = (float*)d_out;

    cudaFuncSetAttribute(k_main, cudaFuncAttributeMaxDynamicSharedMemorySize, SMEM_BYTES);

    k_init<<<1, 256>>>();
    k_colsum<<<512, 256>>>(Ct);
    k_main<<<BB / TB, 256, SMEM_BYTES>>>(Q, Wr, br, Ww, bw, Mem, out);
    k_epilogue<<<1, 256>>>(Mem, age, Wc, bc, out);
}